// round 1
// baseline (speedup 1.0000x reference)
#include <cuda_runtime.h>
#include <cuda_bf16.h>
#include <math.h>

#define D_MODEL 1024
#define N_HEADS 16
#define D_HEAD 64
#define BATCH 2
#define SEQ 2048
#define M_TOT (BATCH * SEQ)   // 4096 tokens

// ---------------- scratch (device globals: allocation-free rule) ----------------
__device__ float g_Q[BATCH * N_HEADS * SEQ * D_HEAD];   // [B,H,S,Dh] 16 MB
__device__ float g_K[BATCH * N_HEADS * SEQ * D_HEAD];
__device__ float g_V[BATCH * N_HEADS * SEQ * D_HEAD];
__device__ float g_C[BATCH * SEQ * D_MODEL];            // context [B,S,D] 16 MB

// =====================================================================
// GEMM core: C[m,n] = sum_k A[m,k]*W[n,k]  (both row-major, K=1024)
// 128x128 tile, BK=8, 256 threads, 8x8 per thread in 4 quadrants.
// =====================================================================
#define BK 8

struct Acc88 { float v[8][8]; };

__device__ __forceinline__ void gemm_tile_128x128(
    const float* __restrict__ A, const float* __restrict__ W,
    int m0, int n0, float acc[8][8])
{
    __shared__ float As[BK][128];
    __shared__ float Bs[BK][128];
    const int tid = threadIdx.x;
    const int lr = tid >> 1;            // 0..127
    const int lk = (tid & 1) * 4;       // 0 or 4
    const int tr = tid >> 4;            // 0..15
    const int tc = tid & 15;            // 0..15

    const float* Ag = A + (size_t)(m0 + lr) * D_MODEL + lk;
    const float* Wg = W + (size_t)(n0 + lr) * D_MODEL + lk;

    float4 a4 = *(const float4*)(Ag);
    float4 w4 = *(const float4*)(Wg);

    for (int k0 = 0; k0 < D_MODEL; k0 += BK) {
        __syncthreads();
        As[lk + 0][lr] = a4.x; As[lk + 1][lr] = a4.y;
        As[lk + 2][lr] = a4.z; As[lk + 3][lr] = a4.w;
        Bs[lk + 0][lr] = w4.x; Bs[lk + 1][lr] = w4.y;
        Bs[lk + 2][lr] = w4.z; Bs[lk + 3][lr] = w4.w;
        __syncthreads();
        if (k0 + BK < D_MODEL) {
            a4 = *(const float4*)(Ag + k0 + BK);
            w4 = *(const float4*)(Wg + k0 + BK);
        }
#pragma unroll
        for (int k = 0; k < BK; k++) {
            float4 a0 = *(const float4*)&As[k][tr * 4];
            float4 a1 = *(const float4*)&As[k][64 + tr * 4];
            float4 b0 = *(const float4*)&Bs[k][tc * 4];
            float4 b1 = *(const float4*)&Bs[k][64 + tc * 4];
            float ar[8] = {a0.x, a0.y, a0.z, a0.w, a1.x, a1.y, a1.z, a1.w};
            float br[8] = {b0.x, b0.y, b0.z, b0.w, b1.x, b1.y, b1.z, b1.w};
#pragma unroll
            for (int i = 0; i < 8; i++)
#pragma unroll
                for (int j = 0; j < 8; j++)
                    acc[i][j] = fmaf(ar[i], br[j], acc[i][j]);
        }
    }
}

// ----- QKV projection: writes Q/K/V scattered into [B,H,S,Dh] -----
__global__ void __launch_bounds__(256, 2)
qkv_gemm_kernel(const float* __restrict__ x,
                const float* __restrict__ wq, const float* __restrict__ wk,
                const float* __restrict__ wv,
                const float* __restrict__ bq, const float* __restrict__ bk,
                const float* __restrict__ bv)
{
    const int m0 = blockIdx.x * 128;
    const int p  = blockIdx.y >> 3;                 // 0:Q 1:K 2:V
    const int n0 = (blockIdx.y & 7) * 128;
    const float* W    = (p == 0) ? wq : (p == 1) ? wk : wv;
    const float* bias = (p == 0) ? bq : (p == 1) ? bk : bv;
    float* dst        = (p == 0) ? g_Q : (p == 1) ? g_K : g_V;

    float acc[8][8];
#pragma unroll
    for (int i = 0; i < 8; i++)
#pragma unroll
        for (int j = 0; j < 8; j++) acc[i][j] = 0.f;

    gemm_tile_128x128(x, W, m0, n0, acc);

    const int tr = threadIdx.x >> 4, tc = threadIdx.x & 15;
#pragma unroll
    for (int ri = 0; ri < 2; ri++) {
#pragma unroll
        for (int i = 0; i < 4; i++) {
            int m = m0 + ri * 64 + tr * 4 + i;
            int b = m >> 11, s = m & (SEQ - 1);
#pragma unroll
            for (int ci = 0; ci < 2; ci++) {
                int n = n0 + ci * 64 + tc * 4;
                int h = n >> 6, d = n & 63;
                float4 r;
                r.x = acc[ri * 4 + i][ci * 4 + 0] + bias[n + 0];
                r.y = acc[ri * 4 + i][ci * 4 + 1] + bias[n + 1];
                r.z = acc[ri * 4 + i][ci * 4 + 2] + bias[n + 2];
                r.w = acc[ri * 4 + i][ci * 4 + 3] + bias[n + 3];
                *(float4*)&dst[(((size_t)(b * N_HEADS + h) * SEQ + s) * D_HEAD) + d] = r;
            }
        }
    }
}

// ----- Output projection: out = ctx @ wo^T + bo, row-major [4096,1024] -----
__global__ void __launch_bounds__(256, 2)
out_gemm_kernel(const float* __restrict__ wo, const float* __restrict__ bo,
                float* __restrict__ out)
{
    const int m0 = blockIdx.x * 128;
    const int n0 = blockIdx.y * 128;
    float acc[8][8];
#pragma unroll
    for (int i = 0; i < 8; i++)
#pragma unroll
        for (int j = 0; j < 8; j++) acc[i][j] = 0.f;

    gemm_tile_128x128(g_C, wo, m0, n0, acc);

    const int tr = threadIdx.x >> 4, tc = threadIdx.x & 15;
#pragma unroll
    for (int ri = 0; ri < 2; ri++)
#pragma unroll
        for (int i = 0; i < 4; i++) {
            int m = m0 + ri * 64 + tr * 4 + i;
#pragma unroll
            for (int ci = 0; ci < 2; ci++) {
                int n = n0 + ci * 64 + tc * 4;
                float4 r;
                r.x = acc[ri * 4 + i][ci * 4 + 0] + bo[n + 0];
                r.y = acc[ri * 4 + i][ci * 4 + 1] + bo[n + 1];
                r.z = acc[ri * 4 + i][ci * 4 + 2] + bo[n + 2];
                r.w = acc[ri * 4 + i][ci * 4 + 3] + bo[n + 3];
                *(float4*)&out[(size_t)m * D_MODEL + n] = r;
            }
        }
}

// =====================================================================
// Flash attention, fp32, causal + padding mask.
// Block: 256 threads handles 64 query rows of one (b,h).
// smem tiles padded to stride 68 floats (272B, 16B-aligned rows).
// =====================================================================
#define TQ 64
#define TK 64
#define SSTR 68   // padded row stride (floats)

__device__ __forceinline__ float hmax16(float v) {
#pragma unroll
    for (int o = 8; o > 0; o >>= 1)
        v = fmaxf(v, __shfl_xor_sync(0xffffffffu, v, o));
    return v;
}
__device__ __forceinline__ float hsum16(float v) {
#pragma unroll
    for (int o = 8; o > 0; o >>= 1)
        v += __shfl_xor_sync(0xffffffffu, v, o);
    return v;
}

__global__ void __launch_bounds__(256)
flash_kernel(const unsigned char* __restrict__ mask)
{
    extern __shared__ float sm[];
    float* Qs = sm;
    float* Ks = sm + TQ * SSTR;
    float* Vs = sm + 2 * TQ * SSTR;
    float* Ps = sm + 3 * TQ * SSTR;

    const int tid = threadIdx.x;
    const int tr = tid >> 4;     // 0..15 -> rows tr*4..+4
    const int tx = tid & 15;
    const int bh = blockIdx.y;
    const int b = bh >> 4, h = bh & 15;
    const int q0 = blockIdx.x * TQ;

    const float* Qg = g_Q + ((size_t)bh * SEQ + q0) * D_HEAD;
    const float* Kg = g_K + (size_t)bh * SEQ * D_HEAD;
    const float* Vg = g_V + (size_t)bh * SEQ * D_HEAD;

    // load Q tile, fold in 1/sqrt(Dh) scale
#pragma unroll
    for (int it = 0; it < 4; it++) {
        int idx = tid + it * 256;          // 1024 float4s
        int r = idx >> 4, c4 = idx & 15;
        float4 v = *(const float4*)(Qg + r * D_HEAD + c4 * 4);
        v.x *= 0.125f; v.y *= 0.125f; v.z *= 0.125f; v.w *= 0.125f;
        *(float4*)&Qs[r * SSTR + c4 * 4] = v;
    }

    float O[4][4];
#pragma unroll
    for (int i = 0; i < 4; i++)
#pragma unroll
        for (int j = 0; j < 4; j++) O[i][j] = 0.f;
    float m_i[4], l_i[4];
#pragma unroll
    for (int i = 0; i < 4; i++) { m_i[i] = -1e30f; l_i[i] = 0.f; }

    const int jmax = blockIdx.x;   // causal: key tiles 0..jmax
    for (int jt = 0; jt <= jmax; jt++) {
        const int k0 = jt * TK;
        __syncthreads();   // previous PV done reading Vs/Ps
        // load K,V tiles
#pragma unroll
        for (int it = 0; it < 4; it++) {
            int idx = tid + it * 256;
            int r = idx >> 4, c4 = idx & 15;
            float4 kv = *(const float4*)(Kg + (k0 + r) * D_HEAD + c4 * 4);
            *(float4*)&Ks[r * SSTR + c4 * 4] = kv;
            float4 vv = *(const float4*)(Vg + (k0 + r) * D_HEAD + c4 * 4);
            *(float4*)&Vs[r * SSTR + c4 * 4] = vv;
        }
        __syncthreads();

        // scores: rows tr*4+i, cols tx+16*jj (spread mapping)
        float s[4][4];
#pragma unroll
        for (int i = 0; i < 4; i++)
#pragma unroll
            for (int jj = 0; jj < 4; jj++) s[i][jj] = 0.f;
#pragma unroll
        for (int d4 = 0; d4 < 16; d4++) {
            float4 q[4], kf[4];
#pragma unroll
            for (int i = 0; i < 4; i++)
                q[i] = *(const float4*)&Qs[(tr * 4 + i) * SSTR + d4 * 4];
#pragma unroll
            for (int jj = 0; jj < 4; jj++)
                kf[jj] = *(const float4*)&Ks[(tx + 16 * jj) * SSTR + d4 * 4];
#pragma unroll
            for (int i = 0; i < 4; i++)
#pragma unroll
                for (int jj = 0; jj < 4; jj++)
                    s[i][jj] += q[i].x * kf[jj].x + q[i].y * kf[jj].y
                              + q[i].z * kf[jj].z + q[i].w * kf[jj].w;
        }

        // masking
        bool mk[4];
#pragma unroll
        for (int jj = 0; jj < 4; jj++)
            mk[jj] = mask[b * SEQ + k0 + tx + 16 * jj] != 0;
#pragma unroll
        for (int i = 0; i < 4; i++) {
            int qrow = q0 + tr * 4 + i;
#pragma unroll
            for (int jj = 0; jj < 4; jj++) {
                int kcol = k0 + tx + 16 * jj;
                if (mk[jj] || kcol > qrow) s[i][jj] = -1e30f;
            }
        }

        // online softmax
        float c[4];
#pragma unroll
        for (int i = 0; i < 4; i++) {
            float rm = fmaxf(fmaxf(s[i][0], s[i][1]), fmaxf(s[i][2], s[i][3]));
            rm = hmax16(rm);
            float mn = fmaxf(m_i[i], rm);
            c[i] = __expf(m_i[i] - mn);
            float rs = 0.f;
#pragma unroll
            for (int jj = 0; jj < 4; jj++) {
                float p = __expf(s[i][jj] - mn);
                s[i][jj] = p;
                rs += p;
            }
            rs = hsum16(rs);
            l_i[i] = l_i[i] * c[i] + rs;
            m_i[i] = mn;
            // write P tile (scatter, conflict-free: bank = tr*16+tx pattern)
#pragma unroll
            for (int jj = 0; jj < 4; jj++)
                Ps[(tr * 4 + i) * SSTR + tx + 16 * jj] = s[i][jj];
#pragma unroll
            for (int j = 0; j < 4; j++) O[i][j] *= c[i];
        }
        __syncthreads();

        // PV: O[row][tx*4..+4] += P[row][kk] * V[kk][col]
#pragma unroll 4
        for (int kk4 = 0; kk4 < 16; kk4++) {
            float4 p4[4];
#pragma unroll
            for (int i = 0; i < 4; i++)
                p4[i] = *(const float4*)&Ps[(tr * 4 + i) * SSTR + kk4 * 4];
#pragma unroll
            for (int u = 0; u < 4; u++) {
                float4 v4 = *(const float4*)&Vs[(kk4 * 4 + u) * SSTR + tx * 4];
                float pv[4] = {p4[0].x, p4[1].x, p4[2].x, p4[3].x};
                if (u == 1) { pv[0] = p4[0].y; pv[1] = p4[1].y; pv[2] = p4[2].y; pv[3] = p4[3].y; }
                if (u == 2) { pv[0] = p4[0].z; pv[1] = p4[1].z; pv[2] = p4[2].z; pv[3] = p4[3].z; }
                if (u == 3) { pv[0] = p4[0].w; pv[1] = p4[1].w; pv[2] = p4[2].w; pv[3] = p4[3].w; }
#pragma unroll
                for (int i = 0; i < 4; i++) {
                    O[i][0] = fmaf(pv[i], v4.x, O[i][0]);
                    O[i][1] = fmaf(pv[i], v4.y, O[i][1]);
                    O[i][2] = fmaf(pv[i], v4.z, O[i][2]);
                    O[i][3] = fmaf(pv[i], v4.w, O[i][3]);
                }
            }
        }
    }

    // normalize and write context in [B,S,H*Dh]
#pragma unroll
    for (int i = 0; i < 4; i++) {
        float inv = 1.0f / l_i[i];
        int srow = q0 + tr * 4 + i;
        float4 r;
        r.x = O[i][0] * inv; r.y = O[i][1] * inv;
        r.z = O[i][2] * inv; r.w = O[i][3] * inv;
        *(float4*)&g_C[((size_t)(b * SEQ + srow) * D_MODEL) + h * D_HEAD + tx * 4] = r;
    }
}

// =====================================================================
extern "C" void kernel_launch(void* const* d_in, const int* in_sizes, int n_in,
                              void* d_out, int out_size)
{
    const float* x  = (const float*)d_in[0];
    const unsigned char* mask = (const unsigned char*)d_in[1];
    const float* wq = (const float*)d_in[2];
    const float* bq = (const float*)d_in[3];
    const float* wk = (const float*)d_in[4];
    const float* bk = (const float*)d_in[5];
    const float* wv = (const float*)d_in[6];
    const float* bv = (const float*)d_in[7];
    const float* wo = (const float*)d_in[8];
    const float* bo = (const float*)d_in[9];
    float* out = (float*)d_out;

    // QKV projections
    qkv_gemm_kernel<<<dim3(M_TOT / 128, 24), 256>>>(x, wq, wk, wv, bq, bk, bv);

    // flash attention
    const int smem = 4 * TQ * SSTR * (int)sizeof(float);   // 69632 B
    static_assert(4 * TQ * SSTR * 4 == 69632, "smem");
    cudaFuncSetAttribute(flash_kernel, cudaFuncAttributeMaxDynamicSharedMemorySize, smem);
    flash_kernel<<<dim3(SEQ / TQ, BATCH * N_HEADS), 256, smem>>>(mask);

    // output projection
    out_gemm_kernel<<<dim3(M_TOT / 128, 8), 256>>>(wo, bo, out);
}

// round 5
// speedup vs baseline: 1.3138x; 1.3138x over previous
#include <cuda_runtime.h>
#include <cuda_bf16.h>
#include <cstdint>
#include <math.h>

#define D_MODEL 1024
#define N_HEADS 16
#define D_HEAD 64
#define BATCH 2
#define SEQ 2048
#define M_TOT (BATCH * SEQ)   // 4096 tokens

// ---------------- scratch (device globals: allocation-free rule) ----------------
__device__ float g_Q[BATCH * N_HEADS * SEQ * D_HEAD];   // [B,H,S,Dh]
__device__ float g_K[BATCH * N_HEADS * SEQ * D_HEAD];
__device__ float g_V[BATCH * N_HEADS * SEQ * D_HEAD];
__device__ __nv_bfloat16 g_xhi[M_TOT * D_MODEL];
__device__ __nv_bfloat16 g_xlo[M_TOT * D_MODEL];
__device__ __nv_bfloat16 g_whi[4 * D_MODEL * D_MODEL];  // q,k,v,o
__device__ __nv_bfloat16 g_wlo[4 * D_MODEL * D_MODEL];
__device__ __nv_bfloat16 g_chi[M_TOT * D_MODEL];        // attention context hi/lo
__device__ __nv_bfloat16 g_clo[M_TOT * D_MODEL];

// =====================================================================
// portable tensor-core PTX (sm_80-era: compiles for plain sm_103)
// =====================================================================
__device__ __forceinline__ uint32_t smem_to_u32(const void* p) {
    uint32_t a;
    asm("{ .reg .u64 t; cvta.to.shared.u64 t, %1; cvt.u32.u64 %0, t; }" : "=r"(a) : "l"(p));
    return a;
}
#define CP_ASYNC16(dst, src) \
    asm volatile("cp.async.cg.shared.global [%0], [%1], 16;" :: "r"(dst), "l"(src))
#define CP_COMMIT() asm volatile("cp.async.commit_group;" ::: "memory")
#define CP_WAIT(n)  asm volatile("cp.async.wait_group %0;" :: "n"(n) : "memory")
#define LDSM_X4(r, a) \
    asm volatile("ldmatrix.sync.aligned.m8n8.x4.shared.b16 {%0,%1,%2,%3}, [%4];" \
        : "=r"((r)[0]), "=r"((r)[1]), "=r"((r)[2]), "=r"((r)[3]) : "r"(a))
#define MMA16816(c, a, b0, b1) \
    asm volatile("mma.sync.aligned.m16n8k16.row.col.f32.bf16.bf16.f32 " \
        "{%0,%1,%2,%3}, {%4,%5,%6,%7}, {%8,%9}, {%0,%1,%2,%3};" \
        : "+f"((c)[0]), "+f"((c)[1]), "+f"((c)[2]), "+f"((c)[3]) \
        : "r"((a)[0]), "r"((a)[1]), "r"((a)[2]), "r"((a)[3]), "r"(b0), "r"(b1))

// =====================================================================
// split-precision HMMA GEMM mainloop:
// acc[128,128] += sum_k A[m0+..,k]*B[n0+..,k], A~Ahi+Alo, B~Bhi+Blo (bf16).
// 256 threads = 8 warps (2m x 4n), warp tile 64x32. KC=32, cp.async 2-stage.
// smem row stride 40 bf16 (80B, odd multiple of 16B -> ldmatrix conflict-free)
// =====================================================================
#define KC 32
#define NCH (D_MODEL / KC)         // 32
#define MSTRB 80                   // bytes per smem row
#define MAT_BYTES (128 * MSTRB)    // 10240
#define STAGE_BYTES (4 * MAT_BYTES)
#define GEMM_SMEM (2 * STAGE_BYTES)   // 81920

__device__ __forceinline__ void load_chunk(
    uint32_t sb, int c,
    const __nv_bfloat16* Ahi, const __nv_bfloat16* Alo,
    const __nv_bfloat16* Bhi, const __nv_bfloat16* Blo, int m0, int n0)
{
    const int tid = threadIdx.x;
    const uint32_t so = sb + (uint32_t)(c & 1) * STAGE_BYTES;
    const int k0 = c * KC;
#pragma unroll
    for (int i = 0; i < 2; i++) {
        int idx = tid + i * 256;            // 0..511
        int r = idx >> 2, cc = idx & 3;
        uint32_t off = (uint32_t)(r * MSTRB + cc * 16);
        size_t ga = (size_t)(m0 + r) * D_MODEL + k0 + cc * 8;
        size_t gb = (size_t)(n0 + r) * D_MODEL + k0 + cc * 8;
        CP_ASYNC16(so + off,                 (const char*)(Ahi + ga));
        CP_ASYNC16(so + MAT_BYTES + off,     (const char*)(Alo + ga));
        CP_ASYNC16(so + 2 * MAT_BYTES + off, (const char*)(Bhi + gb));
        CP_ASYNC16(so + 3 * MAT_BYTES + off, (const char*)(Blo + gb));
    }
    CP_COMMIT();
}

__device__ __forceinline__ void hmma_mainloop(
    const __nv_bfloat16* __restrict__ Ahi, const __nv_bfloat16* __restrict__ Alo,
    const __nv_bfloat16* __restrict__ Bhi, const __nv_bfloat16* __restrict__ Blo,
    int m0, int n0, float acc[4][4][4])
{
    extern __shared__ char smem[];
    const uint32_t sb = smem_to_u32(smem);
    const int tid = threadIdx.x;
    const int lane = tid & 31, wid = tid >> 5;
    const int wm = wid & 1, wn = wid >> 1;

#pragma unroll
    for (int i = 0; i < 4; i++)
#pragma unroll
        for (int j = 0; j < 4; j++)
#pragma unroll
            for (int kk = 0; kk < 4; kk++) acc[i][j][kk] = 0.f;

    // lane-dependent ldmatrix base offsets (bytes)
    const uint32_t laneA = (uint32_t)(((lane & 7) + ((lane >> 3) & 1) * 8 + wm * 64) * MSTRB
                                      + (lane >> 4) * 16);
    const uint32_t laneB = (uint32_t)(((lane & 7) + wn * 32) * MSTRB + (lane >> 3) * 16);

    load_chunk(sb, 0, Ahi, Alo, Bhi, Blo, m0, n0);

    const uint32_t Aoff[3] = {0u, 0u, (uint32_t)MAT_BYTES};
    const uint32_t Boff[3] = {2u * MAT_BYTES, 3u * MAT_BYTES, 2u * MAT_BYTES};

    for (int c = 0; c < NCH; c++) {
        if (c + 1 < NCH) {
            load_chunk(sb, c + 1, Ahi, Alo, Bhi, Blo, m0, n0);
            CP_WAIT(1);
        } else {
            CP_WAIT(0);
        }
        __syncthreads();

        const uint32_t base = sb + (uint32_t)(c & 1) * STAGE_BYTES;
#pragma unroll
        for (int p = 0; p < 3; p++) {
            const uint32_t Ab = base + Aoff[p] + laneA;
            const uint32_t Bb = base + Boff[p] + laneB;
            uint32_t bf[4][4];
#pragma unroll
            for (int nb = 0; nb < 4; nb++)
                LDSM_X4(bf[nb], Bb + nb * (8 * MSTRB));
#pragma unroll
            for (int ks = 0; ks < 2; ks++) {
#pragma unroll
                for (int mb = 0; mb < 4; mb++) {
                    uint32_t af[4];
                    LDSM_X4(af, Ab + mb * (16 * MSTRB) + ks * 32);
#pragma unroll
                    for (int nb = 0; nb < 4; nb++)
                        MMA16816(acc[mb][nb], af, bf[nb][ks * 2], bf[nb][ks * 2 + 1]);
                }
            }
        }
        __syncthreads();   // all warps done with this stage before it is overwritten
    }
}

// ----- QKV projection -----
__global__ void __launch_bounds__(256, 1)
qkv_mma_kernel(const float* __restrict__ bq, const float* __restrict__ bk,
               const float* __restrict__ bv)
{
    const int m0 = blockIdx.x * 128;
    const int p  = blockIdx.y >> 3;                 // 0:Q 1:K 2:V
    const int n0 = (blockIdx.y & 7) * 128;
    const __nv_bfloat16* Bhi = g_whi + (size_t)p * D_MODEL * D_MODEL;
    const __nv_bfloat16* Blo = g_wlo + (size_t)p * D_MODEL * D_MODEL;
    const float* bias = (p == 0) ? bq : (p == 1) ? bk : bv;
    float* dst        = (p == 0) ? g_Q : (p == 1) ? g_K : g_V;

    float acc[4][4][4];
    hmma_mainloop(g_xhi, g_xlo, Bhi, Blo, m0, n0, acc);

    const int lane = threadIdx.x & 31, wid = threadIdx.x >> 5;
    const int wm = wid & 1, wn = wid >> 1;
#pragma unroll
    for (int mb = 0; mb < 4; mb++) {
#pragma unroll
        for (int nb = 0; nb < 4; nb++) {
            int ncol = n0 + wn * 32 + nb * 8 + (lane & 3) * 2;
            float bx = __ldg(bias + ncol), by = __ldg(bias + ncol + 1);
            int h = ncol >> 6, d = ncol & 63;
#pragma unroll
            for (int hh = 0; hh < 2; hh++) {
                int m = m0 + wm * 64 + mb * 16 + (lane >> 2) + hh * 8;
                int b = m >> 11, s = m & (SEQ - 1);
                float2 r;
                r.x = acc[mb][nb][2 * hh + 0] + bx;
                r.y = acc[mb][nb][2 * hh + 1] + by;
                *(float2*)&dst[(((size_t)(b * N_HEADS + h) * SEQ + s) * D_HEAD) + d] = r;
            }
        }
    }
}

// ----- Output projection -----
__global__ void __launch_bounds__(256, 1)
out_mma_kernel(const float* __restrict__ bo, float* __restrict__ out)
{
    const int m0 = blockIdx.x * 128;
    const int n0 = blockIdx.y * 128;
    const __nv_bfloat16* Bhi = g_whi + (size_t)3 * D_MODEL * D_MODEL;
    const __nv_bfloat16* Blo = g_wlo + (size_t)3 * D_MODEL * D_MODEL;

    float acc[4][4][4];
    hmma_mainloop(g_chi, g_clo, Bhi, Blo, m0, n0, acc);

    const int lane = threadIdx.x & 31, wid = threadIdx.x >> 5;
    const int wm = wid & 1, wn = wid >> 1;
#pragma unroll
    for (int mb = 0; mb < 4; mb++) {
#pragma unroll
        for (int nb = 0; nb < 4; nb++) {
            int ncol = n0 + wn * 32 + nb * 8 + (lane & 3) * 2;
            float bx = __ldg(bo + ncol), by = __ldg(bo + ncol + 1);
#pragma unroll
            for (int hh = 0; hh < 2; hh++) {
                int m = m0 + wm * 64 + mb * 16 + (lane >> 2) + hh * 8;
                float2 r;
                r.x = acc[mb][nb][2 * hh + 0] + bx;
                r.y = acc[mb][nb][2 * hh + 1] + by;
                *(float2*)&out[(size_t)m * D_MODEL + ncol] = r;
            }
        }
    }
}

// ----- fp32 -> bf16 hi/lo split -----
__global__ void split_fp32_kernel(const float* __restrict__ src,
                                  __nv_bfloat16* __restrict__ hi,
                                  __nv_bfloat16* __restrict__ lo, int n4)
{
    int i = blockIdx.x * blockDim.x + threadIdx.x;
    if (i >= n4) return;
    float4 v = ((const float4*)src)[i];
    __nv_bfloat16 h0 = __float2bfloat16(v.x), h1 = __float2bfloat16(v.y);
    __nv_bfloat16 h2 = __float2bfloat16(v.z), h3 = __float2bfloat16(v.w);
    __nv_bfloat162* hp = (__nv_bfloat162*)hi;
    hp[2 * i + 0] = __nv_bfloat162(h0, h1);
    hp[2 * i + 1] = __nv_bfloat162(h2, h3);
    __nv_bfloat162* lp = (__nv_bfloat162*)lo;
    lp[2 * i + 0] = __nv_bfloat162(__float2bfloat16(v.x - __bfloat162float(h0)),
                                   __float2bfloat16(v.y - __bfloat162float(h1)));
    lp[2 * i + 1] = __nv_bfloat162(__float2bfloat16(v.z - __bfloat162float(h2)),
                                   __float2bfloat16(v.w - __bfloat162float(h3)));
}

// =====================================================================
// Flash attention, fp32 (unchanged math); epilogue writes bf16 hi/lo context
// =====================================================================
#define TQ 64
#define TK 64
#define SSTR 68

__device__ __forceinline__ float hmax16(float v) {
#pragma unroll
    for (int o = 8; o > 0; o >>= 1) v = fmaxf(v, __shfl_xor_sync(0xffffffffu, v, o));
    return v;
}
__device__ __forceinline__ float hsum16(float v) {
#pragma unroll
    for (int o = 8; o > 0; o >>= 1) v += __shfl_xor_sync(0xffffffffu, v, o);
    return v;
}

__global__ void __launch_bounds__(256)
flash_kernel(const unsigned char* __restrict__ mask)
{
    extern __shared__ float sm[];
    float* Qs = sm;
    float* Ks = sm + TQ * SSTR;
    float* Vs = sm + 2 * TQ * SSTR;
    float* Ps = sm + 3 * TQ * SSTR;

    const int tid = threadIdx.x;
    const int tr = tid >> 4;
    const int tx = tid & 15;
    const int bh = blockIdx.y;
    const int b = bh >> 4, h = bh & 15;
    const int q0 = blockIdx.x * TQ;

    const float* Qg = g_Q + ((size_t)bh * SEQ + q0) * D_HEAD;
    const float* Kg = g_K + (size_t)bh * SEQ * D_HEAD;
    const float* Vg = g_V + (size_t)bh * SEQ * D_HEAD;

#pragma unroll
    for (int it = 0; it < 4; it++) {
        int idx = tid + it * 256;
        int r = idx >> 4, c4 = idx & 15;
        float4 v = *(const float4*)(Qg + r * D_HEAD + c4 * 4);
        v.x *= 0.125f; v.y *= 0.125f; v.z *= 0.125f; v.w *= 0.125f;
        *(float4*)&Qs[r * SSTR + c4 * 4] = v;
    }

    float O[4][4];
#pragma unroll
    for (int i = 0; i < 4; i++)
#pragma unroll
        for (int j = 0; j < 4; j++) O[i][j] = 0.f;
    float m_i[4], l_i[4];
#pragma unroll
    for (int i = 0; i < 4; i++) { m_i[i] = -1e30f; l_i[i] = 0.f; }

    const int jmax = blockIdx.x;
    for (int jt = 0; jt <= jmax; jt++) {
        const int k0 = jt * TK;
        __syncthreads();
#pragma unroll
        for (int it = 0; it < 4; it++) {
            int idx = tid + it * 256;
            int r = idx >> 4, c4 = idx & 15;
            float4 kv = *(const float4*)(Kg + (k0 + r) * D_HEAD + c4 * 4);
            *(float4*)&Ks[r * SSTR + c4 * 4] = kv;
            float4 vv = *(const float4*)(Vg + (k0 + r) * D_HEAD + c4 * 4);
            *(float4*)&Vs[r * SSTR + c4 * 4] = vv;
        }
        __syncthreads();

        float s[4][4];
#pragma unroll
        for (int i = 0; i < 4; i++)
#pragma unroll
            for (int jj = 0; jj < 4; jj++) s[i][jj] = 0.f;
#pragma unroll
        for (int d4 = 0; d4 < 16; d4++) {
            float4 q[4], kf[4];
#pragma unroll
            for (int i = 0; i < 4; i++)
                q[i] = *(const float4*)&Qs[(tr * 4 + i) * SSTR + d4 * 4];
#pragma unroll
            for (int jj = 0; jj < 4; jj++)
                kf[jj] = *(const float4*)&Ks[(tx + 16 * jj) * SSTR + d4 * 4];
#pragma unroll
            for (int i = 0; i < 4; i++)
#pragma unroll
                for (int jj = 0; jj < 4; jj++)
                    s[i][jj] += q[i].x * kf[jj].x + q[i].y * kf[jj].y
                              + q[i].z * kf[jj].z + q[i].w * kf[jj].w;
        }

        bool mk[4];
#pragma unroll
        for (int jj = 0; jj < 4; jj++)
            mk[jj] = mask[b * SEQ + k0 + tx + 16 * jj] != 0;
#pragma unroll
        for (int i = 0; i < 4; i++) {
            int qrow = q0 + tr * 4 + i;
#pragma unroll
            for (int jj = 0; jj < 4; jj++) {
                int kcol = k0 + tx + 16 * jj;
                if (mk[jj] || kcol > qrow) s[i][jj] = -1e30f;
            }
        }

        float c[4];
#pragma unroll
        for (int i = 0; i < 4; i++) {
            float rm = fmaxf(fmaxf(s[i][0], s[i][1]), fmaxf(s[i][2], s[i][3]));
            rm = hmax16(rm);
            float mn = fmaxf(m_i[i], rm);
            c[i] = __expf(m_i[i] - mn);
            float rs = 0.f;
#pragma unroll
            for (int jj = 0; jj < 4; jj++) {
                float p = __expf(s[i][jj] - mn);
                s[i][jj] = p;
                rs += p;
            }
            rs = hsum16(rs);
            l_i[i] = l_i[i] * c[i] + rs;
            m_i[i] = mn;
#pragma unroll
            for (int jj = 0; jj < 4; jj++)
                Ps[(tr * 4 + i) * SSTR + tx + 16 * jj] = s[i][jj];
#pragma unroll
            for (int j = 0; j < 4; j++) O[i][j] *= c[i];
        }
        __syncthreads();

#pragma unroll 4
        for (int kk4 = 0; kk4 < 16; kk4++) {
            float4 p4[4];
#pragma unroll
            for (int i = 0; i < 4; i++)
                p4[i] = *(const float4*)&Ps[(tr * 4 + i) * SSTR + kk4 * 4];
#pragma unroll
            for (int u = 0; u < 4; u++) {
                float4 v4 = *(const float4*)&Vs[(kk4 * 4 + u) * SSTR + tx * 4];
                float pv[4] = {p4[0].x, p4[1].x, p4[2].x, p4[3].x};
                if (u == 1) { pv[0] = p4[0].y; pv[1] = p4[1].y; pv[2] = p4[2].y; pv[3] = p4[3].y; }
                if (u == 2) { pv[0] = p4[0].z; pv[1] = p4[1].z; pv[2] = p4[2].z; pv[3] = p4[3].z; }
                if (u == 3) { pv[0] = p4[0].w; pv[1] = p4[1].w; pv[2] = p4[2].w; pv[3] = p4[3].w; }
#pragma unroll
                for (int i = 0; i < 4; i++) {
                    O[i][0] = fmaf(pv[i], v4.x, O[i][0]);
                    O[i][1] = fmaf(pv[i], v4.y, O[i][1]);
                    O[i][2] = fmaf(pv[i], v4.z, O[i][2]);
                    O[i][3] = fmaf(pv[i], v4.w, O[i][3]);
                }
            }
        }
    }

    // normalize; write bf16 hi/lo context [B,S,D]
#pragma unroll
    for (int i = 0; i < 4; i++) {
        float inv = 1.0f / l_i[i];
        int srow = q0 + tr * 4 + i;
        float rx = O[i][0] * inv, ry = O[i][1] * inv;
        float rz = O[i][2] * inv, rw = O[i][3] * inv;
        size_t off = ((size_t)(b * SEQ + srow) * D_MODEL) + h * D_HEAD + tx * 4;
        __nv_bfloat16 h0 = __float2bfloat16(rx), h1 = __float2bfloat16(ry);
        __nv_bfloat16 h2 = __float2bfloat16(rz), h3 = __float2bfloat16(rw);
        *(__nv_bfloat162*)(g_chi + off)     = __nv_bfloat162(h0, h1);
        *(__nv_bfloat162*)(g_chi + off + 2) = __nv_bfloat162(h2, h3);
        *(__nv_bfloat162*)(g_clo + off) =
            __nv_bfloat162(__float2bfloat16(rx - __bfloat162float(h0)),
                           __float2bfloat16(ry - __bfloat162float(h1)));
        *(__nv_bfloat162*)(g_clo + off + 2) =
            __nv_bfloat162(__float2bfloat16(rz - __bfloat162float(h2)),
                           __float2bfloat16(rw - __bfloat162float(h3)));
    }
}

// =====================================================================
extern "C" void kernel_launch(void* const* d_in, const int* in_sizes, int n_in,
                              void* d_out, int out_size)
{
    const float* x  = (const float*)d_in[0];
    const unsigned char* mask = (const unsigned char*)d_in[1];
    const float* wq = (const float*)d_in[2];
    const float* bq = (const float*)d_in[3];
    const float* wk = (const float*)d_in[4];
    const float* bk = (const float*)d_in[5];
    const float* wv = (const float*)d_in[6];
    const float* bv = (const float*)d_in[7];
    const float* wo = (const float*)d_in[8];
    const float* bo = (const float*)d_in[9];
    float* out = (float*)d_out;

    __nv_bfloat16 *xhi, *xlo, *whi, *wlo;
    cudaGetSymbolAddress((void**)&xhi, g_xhi);
    cudaGetSymbolAddress((void**)&xlo, g_xlo);
    cudaGetSymbolAddress((void**)&whi, g_whi);
    cudaGetSymbolAddress((void**)&wlo, g_wlo);

    const int xn4 = M_TOT * D_MODEL / 4;
    const int wn4 = D_MODEL * D_MODEL / 4;
    split_fp32_kernel<<<xn4 / 256, 256>>>(x, xhi, xlo, xn4);
    split_fp32_kernel<<<wn4 / 256, 256>>>(wq, whi + 0 * (size_t)D_MODEL * D_MODEL,
                                          wlo + 0 * (size_t)D_MODEL * D_MODEL, wn4);
    split_fp32_kernel<<<wn4 / 256, 256>>>(wk, whi + 1 * (size_t)D_MODEL * D_MODEL,
                                          wlo + 1 * (size_t)D_MODEL * D_MODEL, wn4);
    split_fp32_kernel<<<wn4 / 256, 256>>>(wv, whi + 2 * (size_t)D_MODEL * D_MODEL,
                                          wlo + 2 * (size_t)D_MODEL * D_MODEL, wn4);
    split_fp32_kernel<<<wn4 / 256, 256>>>(wo, whi + 3 * (size_t)D_MODEL * D_MODEL,
                                          wlo + 3 * (size_t)D_MODEL * D_MODEL, wn4);

    cudaFuncSetAttribute(qkv_mma_kernel, cudaFuncAttributeMaxDynamicSharedMemorySize, GEMM_SMEM);
    qkv_mma_kernel<<<dim3(M_TOT / 128, 24), 256, GEMM_SMEM>>>(bq, bk, bv);

    const int smem = 4 * TQ * SSTR * (int)sizeof(float);
    cudaFuncSetAttribute(flash_kernel, cudaFuncAttributeMaxDynamicSharedMemorySize, smem);
    flash_kernel<<<dim3(SEQ / TQ, BATCH * N_HEADS), 256, smem>>>(mask);

    cudaFuncSetAttribute(out_mma_kernel, cudaFuncAttributeMaxDynamicSharedMemorySize, GEMM_SMEM);
    out_mma_kernel<<<dim3(M_TOT / 128, 8), 256, GEMM_SMEM>>>(bo, out);
}

// round 11
// speedup vs baseline: 2.0897x; 1.5905x over previous
#include <cuda_runtime.h>
#include <cuda_bf16.h>
#include <cstdint>
#include <math.h>

#define D_MODEL 1024
#define N_HEADS 16
#define D_HEAD 64
#define BATCH 2
#define SEQ 2048
#define M_TOT (BATCH * SEQ)   // 4096 tokens

// ---------------- scratch (device globals: allocation-free rule) ----------------
__device__ __nv_bfloat16 g_Qh[BATCH * N_HEADS * SEQ * D_HEAD];  // pre-scaled by 1/8
__device__ __nv_bfloat16 g_Ql[BATCH * N_HEADS * SEQ * D_HEAD];
__device__ __nv_bfloat16 g_Kh[BATCH * N_HEADS * SEQ * D_HEAD];
__device__ __nv_bfloat16 g_Kl[BATCH * N_HEADS * SEQ * D_HEAD];
__device__ __nv_bfloat16 g_Vh[BATCH * N_HEADS * SEQ * D_HEAD];
__device__ __nv_bfloat16 g_Vl[BATCH * N_HEADS * SEQ * D_HEAD];
__device__ __nv_bfloat16 g_xhi[M_TOT * D_MODEL];
__device__ __nv_bfloat16 g_xlo[M_TOT * D_MODEL];
__device__ __nv_bfloat16 g_whi[4 * D_MODEL * D_MODEL];  // q,k,v,o
__device__ __nv_bfloat16 g_wlo[4 * D_MODEL * D_MODEL];
__device__ __nv_bfloat16 g_chi[M_TOT * D_MODEL];        // attention context hi/lo
__device__ __nv_bfloat16 g_clo[M_TOT * D_MODEL];

// =====================================================================
// portable tensor-core PTX (sm_80-era: compiles for plain sm_103)
// =====================================================================
__device__ __forceinline__ uint32_t smem_to_u32(const void* p) {
    uint32_t a;
    asm("{ .reg .u64 t; cvta.to.shared.u64 t, %1; cvt.u32.u64 %0, t; }" : "=r"(a) : "l"(p));
    return a;
}
#define CP_ASYNC16(dst, src) \
    asm volatile("cp.async.cg.shared.global [%0], [%1], 16;" :: "r"(dst), "l"(src))
#define CP_COMMIT() asm volatile("cp.async.commit_group;" ::: "memory")
#define CP_WAIT(n)  asm volatile("cp.async.wait_group %0;" :: "n"(n) : "memory")
#define LDSM_X4(r, a) \
    asm volatile("ldmatrix.sync.aligned.m8n8.x4.shared.b16 {%0,%1,%2,%3}, [%4];" \
        : "=r"((r)[0]), "=r"((r)[1]), "=r"((r)[2]), "=r"((r)[3]) : "r"(a))
#define LDSM_T4(r, a) \
    asm volatile("ldmatrix.sync.aligned.m8n8.x4.trans.shared.b16 {%0,%1,%2,%3}, [%4];" \
        : "=r"((r)[0]), "=r"((r)[1]), "=r"((r)[2]), "=r"((r)[3]) : "r"(a))
#define MMA16816(c, a, b0, b1) \
    asm volatile("mma.sync.aligned.m16n8k16.row.col.f32.bf16.bf16.f32 " \
        "{%0,%1,%2,%3}, {%4,%5,%6,%7}, {%8,%9}, {%0,%1,%2,%3};" \
        : "+f"((c)[0]), "+f"((c)[1]), "+f"((c)[2]), "+f"((c)[3]) \
        : "r"((a)[0]), "r"((a)[1]), "r"((a)[2]), "r"((a)[3]), "r"(b0), "r"(b1))

// pack (a,b) into bf16x2 hi word and bf16x2 residual lo word
__device__ __forceinline__ void split2(float a, float b, uint32_t& hi, uint32_t& lo) {
    __nv_bfloat16 ha = __float2bfloat16(a);
    __nv_bfloat16 hb = __float2bfloat16(b);
    __nv_bfloat162 th(ha, hb);
    __nv_bfloat162 tl(__float2bfloat16(a - __bfloat162float(ha)),
                      __float2bfloat16(b - __bfloat162float(hb)));
    hi = *(uint32_t*)&th;
    lo = *(uint32_t*)&tl;
}

// =====================================================================
// split-precision HMMA GEMM mainloop (proven in R5, byte-identical logic)
// =====================================================================
#define KC 32
#define NCH (D_MODEL / KC)         // 32
#define MSTRB 80                   // bytes per smem row
#define MAT_BYTES (128 * MSTRB)    // 10240
#define STAGE_BYTES (4 * MAT_BYTES)
#define GEMM_SMEM (2 * STAGE_BYTES)   // 81920

__device__ __forceinline__ void load_chunk(
    uint32_t sb, int c,
    const __nv_bfloat16* Ahi, const __nv_bfloat16* Alo,
    const __nv_bfloat16* Bhi, const __nv_bfloat16* Blo, int m0, int n0)
{
    const int tid = threadIdx.x;
    const uint32_t so = sb + (uint32_t)(c & 1) * STAGE_BYTES;
    const int k0 = c * KC;
#pragma unroll
    for (int i = 0; i < 2; i++) {
        int idx = tid + i * 256;
        int r = idx >> 2, cc = idx & 3;
        uint32_t off = (uint32_t)(r * MSTRB + cc * 16);
        size_t ga = (size_t)(m0 + r) * D_MODEL + k0 + cc * 8;
        size_t gb = (size_t)(n0 + r) * D_MODEL + k0 + cc * 8;
        CP_ASYNC16(so + off,                 (const char*)(Ahi + ga));
        CP_ASYNC16(so + MAT_BYTES + off,     (const char*)(Alo + ga));
        CP_ASYNC16(so + 2 * MAT_BYTES + off, (const char*)(Bhi + gb));
        CP_ASYNC16(so + 3 * MAT_BYTES + off, (const char*)(Blo + gb));
    }
    CP_COMMIT();
}

__device__ __forceinline__ void hmma_mainloop(
    const __nv_bfloat16* __restrict__ Ahi, const __nv_bfloat16* __restrict__ Alo,
    const __nv_bfloat16* __restrict__ Bhi, const __nv_bfloat16* __restrict__ Blo,
    int m0, int n0, float acc[4][4][4])
{
    extern __shared__ char smem[];
    const uint32_t sb = smem_to_u32(smem);
    const int tid = threadIdx.x;
    const int lane = tid & 31, wid = tid >> 5;
    const int wm = wid & 1, wn = wid >> 1;

#pragma unroll
    for (int i = 0; i < 4; i++)
#pragma unroll
        for (int j = 0; j < 4; j++)
#pragma unroll
            for (int kk = 0; kk < 4; kk++) acc[i][j][kk] = 0.f;

    const uint32_t laneA = (uint32_t)(((lane & 15) + wm * 64) * MSTRB + (lane >> 4) * 16);
    const uint32_t laneB = (uint32_t)(((lane & 7) + wn * 32) * MSTRB + (lane >> 3) * 16);

    load_chunk(sb, 0, Ahi, Alo, Bhi, Blo, m0, n0);

    const uint32_t Aoff[3] = {0u, 0u, (uint32_t)MAT_BYTES};
    const uint32_t Boff[3] = {2u * MAT_BYTES, 3u * MAT_BYTES, 2u * MAT_BYTES};

    for (int c = 0; c < NCH; c++) {
        if (c + 1 < NCH) {
            load_chunk(sb, c + 1, Ahi, Alo, Bhi, Blo, m0, n0);
            CP_WAIT(1);
        } else {
            CP_WAIT(0);
        }
        __syncthreads();

        const uint32_t base = sb + (uint32_t)(c & 1) * STAGE_BYTES;
#pragma unroll
        for (int p = 0; p < 3; p++) {
            const uint32_t Ab = base + Aoff[p] + laneA;
            const uint32_t Bb = base + Boff[p] + laneB;
            uint32_t bf[4][4];
#pragma unroll
            for (int nb = 0; nb < 4; nb++)
                LDSM_X4(bf[nb], Bb + nb * (8 * MSTRB));
#pragma unroll
            for (int ks = 0; ks < 2; ks++) {
#pragma unroll
                for (int mb = 0; mb < 4; mb++) {
                    uint32_t af[4];
                    LDSM_X4(af, Ab + mb * (16 * MSTRB) + ks * 32);
#pragma unroll
                    for (int nb = 0; nb < 4; nb++)
                        MMA16816(acc[mb][nb], af, bf[nb][ks * 2], bf[nb][ks * 2 + 1]);
                }
            }
        }
        __syncthreads();
    }
}

// ----- QKV projection: epilogue writes bf16 hi/lo Q(pre-scaled)/K/V [B,H,S,Dh] -----
__global__ void __launch_bounds__(256, 1)
qkv_mma_kernel(const float* __restrict__ bq, const float* __restrict__ bk,
               const float* __restrict__ bv)
{
    const int m0 = blockIdx.x * 128;
    const int p  = blockIdx.y >> 3;                 // 0:Q 1:K 2:V
    const int n0 = (blockIdx.y & 7) * 128;
    const __nv_bfloat16* Bhi = g_whi + (size_t)p * D_MODEL * D_MODEL;
    const __nv_bfloat16* Blo = g_wlo + (size_t)p * D_MODEL * D_MODEL;
    const float* bias = (p == 0) ? bq : (p == 1) ? bk : bv;
    __nv_bfloat16* dh = (p == 0) ? g_Qh : (p == 1) ? g_Kh : g_Vh;
    __nv_bfloat16* dl = (p == 0) ? g_Ql : (p == 1) ? g_Kl : g_Vl;
    const float scale = (p == 0) ? 0.125f : 1.0f;

    float acc[4][4][4];
    hmma_mainloop(g_xhi, g_xlo, Bhi, Blo, m0, n0, acc);

    const int lane = threadIdx.x & 31, wid = threadIdx.x >> 5;
    const int wm = wid & 1, wn = wid >> 1;
#pragma unroll
    for (int mb = 0; mb < 4; mb++) {
#pragma unroll
        for (int nb = 0; nb < 4; nb++) {
            int ncol = n0 + wn * 32 + nb * 8 + (lane & 3) * 2;
            float bx = __ldg(bias + ncol), by = __ldg(bias + ncol + 1);
            int h = ncol >> 6, d = ncol & 63;
#pragma unroll
            for (int hh = 0; hh < 2; hh++) {
                int m = m0 + wm * 64 + mb * 16 + (lane >> 2) + hh * 8;
                int b = m >> 11, s = m & (SEQ - 1);
                float vx = (acc[mb][nb][2 * hh + 0] + bx) * scale;
                float vy = (acc[mb][nb][2 * hh + 1] + by) * scale;
                uint32_t hi, lo;
                split2(vx, vy, hi, lo);
                size_t off = (((size_t)(b * N_HEADS + h) * SEQ + s) * D_HEAD) + d;
                *(uint32_t*)&dh[off] = hi;
                *(uint32_t*)&dl[off] = lo;
            }
        }
    }
}

// ----- Output projection -----
__global__ void __launch_bounds__(256, 1)
out_mma_kernel(const float* __restrict__ bo, float* __restrict__ out)
{
    const int m0 = blockIdx.x * 128;
    const int n0 = blockIdx.y * 128;
    const __nv_bfloat16* Bhi = g_whi + (size_t)3 * D_MODEL * D_MODEL;
    const __nv_bfloat16* Blo = g_wlo + (size_t)3 * D_MODEL * D_MODEL;

    float acc[4][4][4];
    hmma_mainloop(g_chi, g_clo, Bhi, Blo, m0, n0, acc);

    const int lane = threadIdx.x & 31, wid = threadIdx.x >> 5;
    const int wm = wid & 1, wn = wid >> 1;
#pragma unroll
    for (int mb = 0; mb < 4; mb++) {
#pragma unroll
        for (int nb = 0; nb < 4; nb++) {
            int ncol = n0 + wn * 32 + nb * 8 + (lane & 3) * 2;
            float bx = __ldg(bo + ncol), by = __ldg(bo + ncol + 1);
#pragma unroll
            for (int hh = 0; hh < 2; hh++) {
                int m = m0 + wm * 64 + mb * 16 + (lane >> 2) + hh * 8;
                float2 r;
                r.x = acc[mb][nb][2 * hh + 0] + bx;
                r.y = acc[mb][nb][2 * hh + 1] + by;
                *(float2*)&out[(size_t)m * D_MODEL + ncol] = r;
            }
        }
    }
}

// ----- fp32 -> bf16 hi/lo split -----
__global__ void split_fp32_kernel(const float* __restrict__ src,
                                  __nv_bfloat16* __restrict__ hi,
                                  __nv_bfloat16* __restrict__ lo, int n4)
{
    int i = blockIdx.x * blockDim.x + threadIdx.x;
    if (i >= n4) return;
    float4 v = ((const float4*)src)[i];
    uint32_t h01, l01, h23, l23;
    split2(v.x, v.y, h01, l01);
    split2(v.z, v.w, h23, l23);
    ((uint32_t*)hi)[2 * i + 0] = h01;
    ((uint32_t*)hi)[2 * i + 1] = h23;
    ((uint32_t*)lo)[2 * i + 0] = l01;
    ((uint32_t*)lo)[2 * i + 1] = l23;
}

// =====================================================================
// Flash attention on HMMA, split-precision QK^T and PV.
// CTA: 128 threads (4 warps), 64 query rows. Key chunks of 128.
// smem: only K/V hi/lo tiles (Q staged through K region pre-loop) + mask.
// =====================================================================
#define FSTR 144
#define SKH 0
#define SKL (128 * FSTR)           // 18432
#define SVH (2 * 128 * FSTR)       // 36864
#define SVL (3 * 128 * FSTR)       // 55296
#define SMSK (4 * 128 * FSTR)      // 73728
#define FLASH_SMEM (SMSK + 128)    // 73856  -> 3 CTAs/SM

__global__ void __launch_bounds__(128)
flash_mma_kernel(const unsigned char* __restrict__ mask)
{
    extern __shared__ char fsm[];
    const uint32_t sb = smem_to_u32(fsm);
    const int tid = threadIdx.x;
    const int lane = tid & 31, w = tid >> 5;
    const int qt = gridDim.x - 1 - blockIdx.x;   // longest-work CTAs first
    const int bh = blockIdx.y;
    const int b = bh >> 4, h = bh & 15;
    const int q0 = qt * 64;

    const __nv_bfloat16* Qh = g_Qh + ((size_t)bh * SEQ + q0) * D_HEAD;
    const __nv_bfloat16* Ql = g_Ql + ((size_t)bh * SEQ + q0) * D_HEAD;
    const __nv_bfloat16* Kh = g_Kh + (size_t)bh * SEQ * D_HEAD;
    const __nv_bfloat16* Kl = g_Kl + (size_t)bh * SEQ * D_HEAD;
    const __nv_bfloat16* Vh = g_Vh + (size_t)bh * SEQ * D_HEAD;
    const __nv_bfloat16* Vl = g_Vl + (size_t)bh * SEQ * D_HEAD;

    // stage Q hi/lo (64 rows x 64 bf16) through the K-tile smem region
#pragma unroll
    for (int i = 0; i < 4; i++) {
        int idx = tid + i * 128;            // 0..511
        int r = idx >> 3, sg = idx & 7;
        uint32_t off = (uint32_t)(r * FSTR + sg * 16);
        CP_ASYNC16(sb + SKH + off, (const char*)(Qh + r * D_HEAD + sg * 8));
        CP_ASYNC16(sb + SKL + off, (const char*)(Ql + r * D_HEAD + sg * 8));
    }
    CP_COMMIT();
    CP_WAIT(0);
    __syncthreads();

    // Q fragments (held in registers for the whole CTA)
    uint32_t qfh[4][4], qfl[4][4];
    {
        const uint32_t laneQ = sb + (uint32_t)((w * 16 + (lane & 15)) * FSTR + (lane >> 4) * 16);
#pragma unroll
        for (int kk = 0; kk < 4; kk++) {
            LDSM_X4(qfh[kk], laneQ + SKH + kk * 32);
            LDSM_X4(qfl[kk], laneQ + SKL + kk * 32);
        }
    }

    float o[8][4];
#pragma unroll
    for (int i = 0; i < 8; i++)
#pragma unroll
        for (int j = 0; j < 4; j++) o[i][j] = 0.f;
    float mrow[2] = {-1e30f, -1e30f};
    float lrow[2] = {0.f, 0.f};

    const int nchunk = qt / 2 + 1;
    for (int c = 0; c < nchunk; c++) {
        const int k0 = c * 128;
        __syncthreads();   // prior chunk (and Q-staging reads) done with smem
        // load K/V hi/lo chunk; mask via plain byte loads
#pragma unroll
        for (int i = 0; i < 8; i++) {
            int idx = tid + i * 128;        // 0..1023
            int r = idx >> 3, sg = idx & 7;
            uint32_t off = (uint32_t)(r * FSTR + sg * 16);
            size_t g = (size_t)(k0 + r) * D_HEAD + sg * 8;
            CP_ASYNC16(sb + SKH + off, (const char*)(Kh + g));
            CP_ASYNC16(sb + SKL + off, (const char*)(Kl + g));
            CP_ASYNC16(sb + SVH + off, (const char*)(Vh + g));
            CP_ASYNC16(sb + SVL + off, (const char*)(Vl + g));
        }
        fsm[SMSK + tid] = (char)mask[b * SEQ + k0 + tid];
        CP_COMMIT();
        CP_WAIT(0);
        __syncthreads();

        // ---- S = Q K^T (3 split passes) ----
        float s[16][4];
#pragma unroll
        for (int nb = 0; nb < 16; nb++)
#pragma unroll
            for (int j = 0; j < 4; j++) s[nb][j] = 0.f;

        const uint32_t laneKB = sb + (uint32_t)((lane & 7) * FSTR + (lane >> 3) * 16);
#pragma unroll
        for (int p = 0; p < 3; p++) {
            const uint32_t kbase = laneKB + (p == 1 ? SKL : SKH);
            uint32_t (*qq)[4] = (p == 2) ? qfl : qfh;
#pragma unroll
            for (int kk2 = 0; kk2 < 2; kk2++) {
#pragma unroll
                for (int nb = 0; nb < 16; nb++) {
                    uint32_t bf[4];
                    LDSM_X4(bf, kbase + nb * (8 * FSTR) + kk2 * 64);
                    MMA16816(s[nb], qq[2 * kk2],     bf[0], bf[1]);
                    MMA16816(s[nb], qq[2 * kk2 + 1], bf[2], bf[3]);
                }
            }
        }

        // ---- mask ----
#pragma unroll
        for (int nb = 0; nb < 16; nb++) {
            int col0 = nb * 8 + (lane & 3) * 2;
            unsigned char mk0 = fsm[SMSK + col0], mk1 = fsm[SMSK + col0 + 1];
            int kc0 = k0 + col0;
#pragma unroll
            for (int h2 = 0; h2 < 2; h2++) {
                int qrow = q0 + w * 16 + (lane >> 2) + h2 * 8;
                if (mk0 || kc0 > qrow)     s[nb][h2 * 2 + 0] = -1e30f;
                if (mk1 || kc0 + 1 > qrow) s[nb][h2 * 2 + 1] = -1e30f;
            }
        }

        // ---- online softmax (rows live in lane quads) ----
#pragma unroll
        for (int h2 = 0; h2 < 2; h2++) {
            float mx = -1e30f;
#pragma unroll
            for (int nb = 0; nb < 16; nb++)
                mx = fmaxf(mx, fmaxf(s[nb][h2 * 2], s[nb][h2 * 2 + 1]));
            mx = fmaxf(mx, __shfl_xor_sync(0xffffffffu, mx, 1));
            mx = fmaxf(mx, __shfl_xor_sync(0xffffffffu, mx, 2));
            float mn = fmaxf(mrow[h2], mx);
            float alpha = __expf(mrow[h2] - mn);
            mrow[h2] = mn;
            float rs = 0.f;
#pragma unroll
            for (int nb = 0; nb < 16; nb++) {
                float p0 = __expf(s[nb][h2 * 2]     - mn);
                float p1 = __expf(s[nb][h2 * 2 + 1] - mn);
                s[nb][h2 * 2] = p0; s[nb][h2 * 2 + 1] = p1;
                rs += p0 + p1;
            }
            rs += __shfl_xor_sync(0xffffffffu, rs, 1);
            rs += __shfl_xor_sync(0xffffffffu, rs, 2);
            lrow[h2] = lrow[h2] * alpha + rs;
#pragma unroll
            for (int nbo = 0; nbo < 8; nbo++) {
                o[nbo][h2 * 2]     *= alpha;
                o[nbo][h2 * 2 + 1] *= alpha;
            }
        }

        // ---- O += P V (3 split passes; P from registers, V via ldmatrix.trans) ----
#pragma unroll
        for (int kk = 0; kk < 8; kk++) {
            uint32_t ah[4], al[4];
            split2(s[2 * kk][0],     s[2 * kk][1],     ah[0], al[0]);
            split2(s[2 * kk][2],     s[2 * kk][3],     ah[1], al[1]);
            split2(s[2 * kk + 1][0], s[2 * kk + 1][1], ah[2], al[2]);
            split2(s[2 * kk + 1][2], s[2 * kk + 1][3], ah[3], al[3]);
            const uint32_t laneV = sb + (uint32_t)(
                (kk * 16 + (lane & 15)) * FSTR + (lane >> 4) * 16);
#pragma unroll
            for (int ng = 0; ng < 4; ng++) {
                uint32_t bh4[4], bl4[4];
                LDSM_T4(bh4, laneV + SVH + ng * 32);
                LDSM_T4(bl4, laneV + SVL + ng * 32);
                MMA16816(o[2 * ng],     ah, bh4[0], bh4[1]);
                MMA16816(o[2 * ng + 1], ah, bh4[2], bh4[3]);
                MMA16816(o[2 * ng],     ah, bl4[0], bl4[1]);
                MMA16816(o[2 * ng + 1], ah, bl4[2], bl4[3]);
                MMA16816(o[2 * ng],     al, bh4[0], bh4[1]);
                MMA16816(o[2 * ng + 1], al, bh4[2], bh4[3]);
            }
        }
    }

    // ---- epilogue: normalize, write bf16 hi/lo context [B,S,D] ----
#pragma unroll
    for (int h2 = 0; h2 < 2; h2++) {
        float inv = 1.0f / lrow[h2];
        int srow = q0 + w * 16 + (lane >> 2) + h2 * 8;
        size_t base = (size_t)(b * SEQ + srow) * D_MODEL + h * D_HEAD;
#pragma unroll
        for (int nbo = 0; nbo < 8; nbo++) {
            int dcol = nbo * 8 + (lane & 3) * 2;
            uint32_t hi, lo;
            split2(o[nbo][h2 * 2] * inv, o[nbo][h2 * 2 + 1] * inv, hi, lo);
            *(uint32_t*)&g_chi[base + dcol] = hi;
            *(uint32_t*)&g_clo[base + dcol] = lo;
        }
    }
}

// =====================================================================
extern "C" void kernel_launch(void* const* d_in, const int* in_sizes, int n_in,
                              void* d_out, int out_size)
{
    const float* x  = (const float*)d_in[0];
    const unsigned char* mask = (const unsigned char*)d_in[1];
    const float* wq = (const float*)d_in[2];
    const float* bq = (const float*)d_in[3];
    const float* wk = (const float*)d_in[4];
    const float* bk = (const float*)d_in[5];
    const float* wv = (const float*)d_in[6];
    const float* bv = (const float*)d_in[7];
    const float* wo = (const float*)d_in[8];
    const float* bo = (const float*)d_in[9];
    float* out = (float*)d_out;

    __nv_bfloat16 *xhi, *xlo, *whi, *wlo;
    cudaGetSymbolAddress((void**)&xhi, g_xhi);
    cudaGetSymbolAddress((void**)&xlo, g_xlo);
    cudaGetSymbolAddress((void**)&whi, g_whi);
    cudaGetSymbolAddress((void**)&wlo, g_wlo);

    const int xn4 = M_TOT * D_MODEL / 4;
    const int wn4 = D_MODEL * D_MODEL / 4;
    split_fp32_kernel<<<xn4 / 256, 256>>>(x, xhi, xlo, xn4);
    split_fp32_kernel<<<wn4 / 256, 256>>>(wq, whi + 0 * (size_t)D_MODEL * D_MODEL,
                                          wlo + 0 * (size_t)D_MODEL * D_MODEL, wn4);
    split_fp32_kernel<<<wn4 / 256, 256>>>(wk, whi + 1 * (size_t)D_MODEL * D_MODEL,
                                          wlo + 1 * (size_t)D_MODEL * D_MODEL, wn4);
    split_fp32_kernel<<<wn4 / 256, 256>>>(wv, whi + 2 * (size_t)D_MODEL * D_MODEL,
                                          wlo + 2 * (size_t)D_MODEL * D_MODEL, wn4);
    split_fp32_kernel<<<wn4 / 256, 256>>>(wo, whi + 3 * (size_t)D_MODEL * D_MODEL,
                                          wlo + 3 * (size_t)D_MODEL * D_MODEL, wn4);

    cudaFuncSetAttribute(qkv_mma_kernel, cudaFuncAttributeMaxDynamicSharedMemorySize, GEMM_SMEM);
    qkv_mma_kernel<<<dim3(M_TOT / 128, 24), 256, GEMM_SMEM>>>(bq, bk, bv);

    cudaFuncSetAttribute(flash_mma_kernel, cudaFuncAttributeMaxDynamicSharedMemorySize, FLASH_SMEM);
    flash_mma_kernel<<<dim3(SEQ / 64, BATCH * N_HEADS), 128, FLASH_SMEM>>>(mask);

    cudaFuncSetAttribute(out_mma_kernel, cudaFuncAttributeMaxDynamicSharedMemorySize, GEMM_SMEM);
    out_mma_kernel<<<dim3(M_TOT / 128, 8), 256, GEMM_SMEM>>>(bo, out);
}

// round 15
// speedup vs baseline: 2.2964x; 1.0989x over previous
#include <cuda_runtime.h>
#include <cuda_bf16.h>
#include <cstdint>
#include <math.h>

#define D_MODEL 1024
#define N_HEADS 16
#define D_HEAD 64
#define BATCH 2
#define SEQ 2048
#define M_TOT (BATCH * SEQ)   // 4096 tokens

// ---------------- scratch (device globals: allocation-free rule) ----------------
__device__ __nv_bfloat16 g_Qh[BATCH * N_HEADS * SEQ * D_HEAD];  // pre-scaled by 1/8
__device__ __nv_bfloat16 g_Ql[BATCH * N_HEADS * SEQ * D_HEAD];
__device__ __nv_bfloat16 g_Kh[BATCH * N_HEADS * SEQ * D_HEAD];
__device__ __nv_bfloat16 g_Kl[BATCH * N_HEADS * SEQ * D_HEAD];
__device__ __nv_bfloat16 g_Vh[BATCH * N_HEADS * SEQ * D_HEAD];
__device__ __nv_bfloat16 g_Vl[BATCH * N_HEADS * SEQ * D_HEAD];
__device__ __nv_bfloat16 g_xhi[M_TOT * D_MODEL];
__device__ __nv_bfloat16 g_xlo[M_TOT * D_MODEL];
__device__ __nv_bfloat16 g_whi[4 * D_MODEL * D_MODEL];  // q,k,v,o
__device__ __nv_bfloat16 g_wlo[4 * D_MODEL * D_MODEL];
__device__ __nv_bfloat16 g_chi[M_TOT * D_MODEL];        // attention context hi/lo
__device__ __nv_bfloat16 g_clo[M_TOT * D_MODEL];

// =====================================================================
// portable tensor-core PTX (sm_80-era: compiles for plain sm_103)
// =====================================================================
__device__ __forceinline__ uint32_t smem_to_u32(const void* p) {
    uint32_t a;
    asm("{ .reg .u64 t; cvta.to.shared.u64 t, %1; cvt.u32.u64 %0, t; }" : "=r"(a) : "l"(p));
    return a;
}
#define CP_ASYNC16(dst, src) \
    asm volatile("cp.async.cg.shared.global [%0], [%1], 16;" :: "r"(dst), "l"(src))
#define CP_COMMIT() asm volatile("cp.async.commit_group;" ::: "memory")
#define CP_WAIT(n)  asm volatile("cp.async.wait_group %0;" :: "n"(n) : "memory")
#define LDSM_X4(r, a) \
    asm volatile("ldmatrix.sync.aligned.m8n8.x4.shared.b16 {%0,%1,%2,%3}, [%4];" \
        : "=r"((r)[0]), "=r"((r)[1]), "=r"((r)[2]), "=r"((r)[3]) : "r"(a))
#define LDSM_T4(r, a) \
    asm volatile("ldmatrix.sync.aligned.m8n8.x4.trans.shared.b16 {%0,%1,%2,%3}, [%4];" \
        : "=r"((r)[0]), "=r"((r)[1]), "=r"((r)[2]), "=r"((r)[3]) : "r"(a))
#define MMA16816(c, a, b0, b1) \
    asm volatile("mma.sync.aligned.m16n8k16.row.col.f32.bf16.bf16.f32 " \
        "{%0,%1,%2,%3}, {%4,%5,%6,%7}, {%8,%9}, {%0,%1,%2,%3};" \
        : "+f"((c)[0]), "+f"((c)[1]), "+f"((c)[2]), "+f"((c)[3]) \
        : "r"((a)[0]), "r"((a)[1]), "r"((a)[2]), "r"((a)[3]), "r"(b0), "r"(b1))

// pack (a,b) into bf16x2 hi word and bf16x2 residual lo word
__device__ __forceinline__ void split2(float a, float b, uint32_t& hi, uint32_t& lo) {
    __nv_bfloat16 ha = __float2bfloat16(a);
    __nv_bfloat16 hb = __float2bfloat16(b);
    __nv_bfloat162 th(ha, hb);
    __nv_bfloat162 tl(__float2bfloat16(a - __bfloat162float(ha)),
                      __float2bfloat16(b - __bfloat162float(hb)));
    hi = *(uint32_t*)&th;
    lo = *(uint32_t*)&tl;
}

// =====================================================================
// split-precision HMMA GEMM mainloop (logic proven in R5/R11)
// =====================================================================
#define KC 32
#define NCH (D_MODEL / KC)         // 32
#define MSTRB 80                   // bytes per smem row
#define MAT_BYTES (128 * MSTRB)    // 10240
#define STAGE_BYTES (4 * MAT_BYTES)
#define GEMM_SMEM (2 * STAGE_BYTES)   // 81920 -> 2 CTAs/SM

__device__ __forceinline__ void load_chunk(
    uint32_t sb, int c,
    const __nv_bfloat16* Ahi, const __nv_bfloat16* Alo,
    const __nv_bfloat16* Bhi, const __nv_bfloat16* Blo, int m0, int n0)
{
    const int tid = threadIdx.x;
    const uint32_t so = sb + (uint32_t)(c & 1) * STAGE_BYTES;
    const int k0 = c * KC;
#pragma unroll
    for (int i = 0; i < 2; i++) {
        int idx = tid + i * 256;
        int r = idx >> 2, cc = idx & 3;
        uint32_t off = (uint32_t)(r * MSTRB + cc * 16);
        size_t ga = (size_t)(m0 + r) * D_MODEL + k0 + cc * 8;
        size_t gb = (size_t)(n0 + r) * D_MODEL + k0 + cc * 8;
        CP_ASYNC16(so + off,                 (const char*)(Ahi + ga));
        CP_ASYNC16(so + MAT_BYTES + off,     (const char*)(Alo + ga));
        CP_ASYNC16(so + 2 * MAT_BYTES + off, (const char*)(Bhi + gb));
        CP_ASYNC16(so + 3 * MAT_BYTES + off, (const char*)(Blo + gb));
    }
    CP_COMMIT();
}

__device__ __forceinline__ void hmma_mainloop(
    const __nv_bfloat16* __restrict__ Ahi, const __nv_bfloat16* __restrict__ Alo,
    const __nv_bfloat16* __restrict__ Bhi, const __nv_bfloat16* __restrict__ Blo,
    int m0, int n0, float acc[4][4][4])
{
    extern __shared__ char smem[];
    const uint32_t sb = smem_to_u32(smem);
    const int tid = threadIdx.x;
    const int lane = tid & 31, wid = tid >> 5;
    const int wm = wid & 1, wn = wid >> 1;

#pragma unroll
    for (int i = 0; i < 4; i++)
#pragma unroll
        for (int j = 0; j < 4; j++)
#pragma unroll
            for (int kk = 0; kk < 4; kk++) acc[i][j][kk] = 0.f;

    const uint32_t laneA = (uint32_t)(((lane & 15) + wm * 64) * MSTRB + (lane >> 4) * 16);
    const uint32_t laneB = (uint32_t)(((lane & 7) + wn * 32) * MSTRB + (lane >> 3) * 16);

    load_chunk(sb, 0, Ahi, Alo, Bhi, Blo, m0, n0);

    const uint32_t Aoff[3] = {0u, 0u, (uint32_t)MAT_BYTES};
    const uint32_t Boff[3] = {2u * MAT_BYTES, 3u * MAT_BYTES, 2u * MAT_BYTES};

    for (int c = 0; c < NCH; c++) {
        if (c + 1 < NCH) {
            load_chunk(sb, c + 1, Ahi, Alo, Bhi, Blo, m0, n0);
            CP_WAIT(1);
        } else {
            CP_WAIT(0);
        }
        __syncthreads();

        const uint32_t base = sb + (uint32_t)(c & 1) * STAGE_BYTES;
#pragma unroll
        for (int p = 0; p < 3; p++) {
            const uint32_t Ab = base + Aoff[p] + laneA;
            const uint32_t Bb = base + Boff[p] + laneB;
            uint32_t bf[4][4];
#pragma unroll
            for (int nb = 0; nb < 4; nb++)
                LDSM_X4(bf[nb], Bb + nb * (8 * MSTRB));
#pragma unroll
            for (int ks = 0; ks < 2; ks++) {
#pragma unroll
                for (int mb = 0; mb < 4; mb++) {
                    uint32_t af[4];
                    LDSM_X4(af, Ab + mb * (16 * MSTRB) + ks * 32);
#pragma unroll
                    for (int nb = 0; nb < 4; nb++)
                        MMA16816(acc[mb][nb], af, bf[nb][ks * 2], bf[nb][ks * 2 + 1]);
                }
            }
        }
        __syncthreads();
    }
}

// ----- QKV projection: epilogue writes bf16 hi/lo Q(pre-scaled)/K/V [B,H,S,Dh] -----
__global__ void __launch_bounds__(256, 2)
qkv_mma_kernel(const float* __restrict__ bq, const float* __restrict__ bk,
               const float* __restrict__ bv)
{
    const int m0 = blockIdx.x * 128;
    const int p  = blockIdx.y >> 3;                 // 0:Q 1:K 2:V
    const int n0 = (blockIdx.y & 7) * 128;
    const __nv_bfloat16* Bhi = g_whi + (size_t)p * D_MODEL * D_MODEL;
    const __nv_bfloat16* Blo = g_wlo + (size_t)p * D_MODEL * D_MODEL;
    const float* bias = (p == 0) ? bq : (p == 1) ? bk : bv;
    __nv_bfloat16* dh = (p == 0) ? g_Qh : (p == 1) ? g_Kh : g_Vh;
    __nv_bfloat16* dl = (p == 0) ? g_Ql : (p == 1) ? g_Kl : g_Vl;
    const float scale = (p == 0) ? 0.125f : 1.0f;

    float acc[4][4][4];
    hmma_mainloop(g_xhi, g_xlo, Bhi, Blo, m0, n0, acc);

    const int lane = threadIdx.x & 31, wid = threadIdx.x >> 5;
    const int wm = wid & 1, wn = wid >> 1;
#pragma unroll
    for (int mb = 0; mb < 4; mb++) {
#pragma unroll
        for (int nb = 0; nb < 4; nb++) {
            int ncol = n0 + wn * 32 + nb * 8 + (lane & 3) * 2;
            float bx = __ldg(bias + ncol), by = __ldg(bias + ncol + 1);
            int h = ncol >> 6, d = ncol & 63;
#pragma unroll
            for (int hh = 0; hh < 2; hh++) {
                int m = m0 + wm * 64 + mb * 16 + (lane >> 2) + hh * 8;
                int b = m >> 11, s = m & (SEQ - 1);
                float vx = (acc[mb][nb][2 * hh + 0] + bx) * scale;
                float vy = (acc[mb][nb][2 * hh + 1] + by) * scale;
                uint32_t hi, lo;
                split2(vx, vy, hi, lo);
                size_t off = (((size_t)(b * N_HEADS + h) * SEQ + s) * D_HEAD) + d;
                *(uint32_t*)&dh[off] = hi;
                *(uint32_t*)&dl[off] = lo;
            }
        }
    }
}

// ----- Output projection -----
__global__ void __launch_bounds__(256, 2)
out_mma_kernel(const float* __restrict__ bo, float* __restrict__ out)
{
    const int m0 = blockIdx.x * 128;
    const int n0 = blockIdx.y * 128;
    const __nv_bfloat16* Bhi = g_whi + (size_t)3 * D_MODEL * D_MODEL;
    const __nv_bfloat16* Blo = g_wlo + (size_t)3 * D_MODEL * D_MODEL;

    float acc[4][4][4];
    hmma_mainloop(g_chi, g_clo, Bhi, Blo, m0, n0, acc);

    const int lane = threadIdx.x & 31, wid = threadIdx.x >> 5;
    const int wm = wid & 1, wn = wid >> 1;
#pragma unroll
    for (int mb = 0; mb < 4; mb++) {
#pragma unroll
        for (int nb = 0; nb < 4; nb++) {
            int ncol = n0 + wn * 32 + nb * 8 + (lane & 3) * 2;
            float bx = __ldg(bo + ncol), by = __ldg(bo + ncol + 1);
#pragma unroll
            for (int hh = 0; hh < 2; hh++) {
                int m = m0 + wm * 64 + mb * 16 + (lane >> 2) + hh * 8;
                float2 r;
                r.x = acc[mb][nb][2 * hh + 0] + bx;
                r.y = acc[mb][nb][2 * hh + 1] + by;
                *(float2*)&out[(size_t)m * D_MODEL + ncol] = r;
            }
        }
    }
}

// ----- fused fp32 -> bf16 hi/lo split for x and all 4 weights -----
#define XN4 (M_TOT * D_MODEL / 4)      // 1048576
#define WN4 (D_MODEL * D_MODEL / 4)    // 262144
#define SPLIT_TOT (XN4 + 4 * WN4)      // 2097152

__global__ void split_all_kernel(const float* __restrict__ x,
                                 const float* __restrict__ wq,
                                 const float* __restrict__ wk,
                                 const float* __restrict__ wv,
                                 const float* __restrict__ wo)
{
    int i = blockIdx.x * blockDim.x + threadIdx.x;
    if (i >= SPLIT_TOT) return;
    const float* src;
    __nv_bfloat16 *hi, *lo;
    int off;
    if (i < XN4) {
        src = x; hi = g_xhi; lo = g_xlo; off = i;
    } else {
        int i2 = i - XN4;
        int seg = i2 / WN4;            // 0..3
        off = i2 - seg * WN4;
        src = (seg == 0) ? wq : (seg == 1) ? wk : (seg == 2) ? wv : wo;
        hi = g_whi + (size_t)seg * D_MODEL * D_MODEL;
        lo = g_wlo + (size_t)seg * D_MODEL * D_MODEL;
    }
    float4 v = ((const float4*)src)[off];
    uint32_t h01, l01, h23, l23;
    split2(v.x, v.y, h01, l01);
    split2(v.z, v.w, h23, l23);
    ((uint32_t*)hi)[2 * off + 0] = h01;
    ((uint32_t*)hi)[2 * off + 1] = h23;
    ((uint32_t*)lo)[2 * off + 0] = l01;
    ((uint32_t*)lo)[2 * off + 1] = l23;
}

// =====================================================================
// Flash attention on HMMA — byte-identical to the R11 version that passed.
// CTA: 128 threads (4 warps), 64 query rows. Key chunks of 128.
// =====================================================================
#define FSTR 144
#define SKH 0
#define SKL (128 * FSTR)           // 18432
#define SVH (2 * 128 * FSTR)       // 36864
#define SVL (3 * 128 * FSTR)       // 55296
#define SMSK (4 * 128 * FSTR)      // 73728
#define FLASH_SMEM (SMSK + 128)    // 73856  -> 3 CTAs/SM

__global__ void __launch_bounds__(128)
flash_mma_kernel(const unsigned char* __restrict__ mask)
{
    extern __shared__ char fsm[];
    const uint32_t sb = smem_to_u32(fsm);
    const int tid = threadIdx.x;
    const int lane = tid & 31, w = tid >> 5;
    const int qt = gridDim.x - 1 - blockIdx.x;   // longest-work CTAs first
    const int bh = blockIdx.y;
    const int b = bh >> 4, h = bh & 15;
    const int q0 = qt * 64;

    const __nv_bfloat16* Qh = g_Qh + ((size_t)bh * SEQ + q0) * D_HEAD;
    const __nv_bfloat16* Ql = g_Ql + ((size_t)bh * SEQ + q0) * D_HEAD;
    const __nv_bfloat16* Kh = g_Kh + (size_t)bh * SEQ * D_HEAD;
    const __nv_bfloat16* Kl = g_Kl + (size_t)bh * SEQ * D_HEAD;
    const __nv_bfloat16* Vh = g_Vh + (size_t)bh * SEQ * D_HEAD;
    const __nv_bfloat16* Vl = g_Vl + (size_t)bh * SEQ * D_HEAD;

    // stage Q hi/lo (64 rows x 64 bf16) through the K-tile smem region
#pragma unroll
    for (int i = 0; i < 4; i++) {
        int idx = tid + i * 128;            // 0..511
        int r = idx >> 3, sg = idx & 7;
        uint32_t off = (uint32_t)(r * FSTR + sg * 16);
        CP_ASYNC16(sb + SKH + off, (const char*)(Qh + r * D_HEAD + sg * 8));
        CP_ASYNC16(sb + SKL + off, (const char*)(Ql + r * D_HEAD + sg * 8));
    }
    CP_COMMIT();
    CP_WAIT(0);
    __syncthreads();

    // Q fragments (held in registers for the whole CTA)
    uint32_t qfh[4][4], qfl[4][4];
    {
        const uint32_t laneQ = sb + (uint32_t)((w * 16 + (lane & 15)) * FSTR + (lane >> 4) * 16);
#pragma unroll
        for (int kk = 0; kk < 4; kk++) {
            LDSM_X4(qfh[kk], laneQ + SKH + kk * 32);
            LDSM_X4(qfl[kk], laneQ + SKL + kk * 32);
        }
    }

    float o[8][4];
#pragma unroll
    for (int i = 0; i < 8; i++)
#pragma unroll
        for (int j = 0; j < 4; j++) o[i][j] = 0.f;
    float mrow[2] = {-1e30f, -1e30f};
    float lrow[2] = {0.f, 0.f};

    const int nchunk = qt / 2 + 1;
    for (int c = 0; c < nchunk; c++) {
        const int k0 = c * 128;
        __syncthreads();   // prior chunk (and Q-staging reads) done with smem
        // load K/V hi/lo chunk; mask via plain byte loads
#pragma unroll
        for (int i = 0; i < 8; i++) {
            int idx = tid + i * 128;        // 0..1023
            int r = idx >> 3, sg = idx & 7;
            uint32_t off = (uint32_t)(r * FSTR + sg * 16);
            size_t g = (size_t)(k0 + r) * D_HEAD + sg * 8;
            CP_ASYNC16(sb + SKH + off, (const char*)(Kh + g));
            CP_ASYNC16(sb + SKL + off, (const char*)(Kl + g));
            CP_ASYNC16(sb + SVH + off, (const char*)(Vh + g));
            CP_ASYNC16(sb + SVL + off, (const char*)(Vl + g));
        }
        fsm[SMSK + tid] = (char)mask[b * SEQ + k0 + tid];
        CP_COMMIT();
        CP_WAIT(0);
        __syncthreads();

        // ---- S = Q K^T (3 split passes) ----
        float s[16][4];
#pragma unroll
        for (int nb = 0; nb < 16; nb++)
#pragma unroll
            for (int j = 0; j < 4; j++) s[nb][j] = 0.f;

        const uint32_t laneKB = sb + (uint32_t)((lane & 7) * FSTR + (lane >> 3) * 16);
#pragma unroll
        for (int p = 0; p < 3; p++) {
            const uint32_t kbase = laneKB + (p == 1 ? SKL : SKH);
            uint32_t (*qq)[4] = (p == 2) ? qfl : qfh;
#pragma unroll
            for (int kk2 = 0; kk2 < 2; kk2++) {
#pragma unroll
                for (int nb = 0; nb < 16; nb++) {
                    uint32_t bf[4];
                    LDSM_X4(bf, kbase + nb * (8 * FSTR) + kk2 * 64);
                    MMA16816(s[nb], qq[2 * kk2],     bf[0], bf[1]);
                    MMA16816(s[nb], qq[2 * kk2 + 1], bf[2], bf[3]);
                }
            }
        }

        // ---- mask ----
#pragma unroll
        for (int nb = 0; nb < 16; nb++) {
            int col0 = nb * 8 + (lane & 3) * 2;
            unsigned char mk0 = fsm[SMSK + col0], mk1 = fsm[SMSK + col0 + 1];
            int kc0 = k0 + col0;
#pragma unroll
            for (int h2 = 0; h2 < 2; h2++) {
                int qrow = q0 + w * 16 + (lane >> 2) + h2 * 8;
                if (mk0 || kc0 > qrow)     s[nb][h2 * 2 + 0] = -1e30f;
                if (mk1 || kc0 + 1 > qrow) s[nb][h2 * 2 + 1] = -1e30f;
            }
        }

        // ---- online softmax (rows live in lane quads) ----
#pragma unroll
        for (int h2 = 0; h2 < 2; h2++) {
            float mx = -1e30f;
#pragma unroll
            for (int nb = 0; nb < 16; nb++)
                mx = fmaxf(mx, fmaxf(s[nb][h2 * 2], s[nb][h2 * 2 + 1]));
            mx = fmaxf(mx, __shfl_xor_sync(0xffffffffu, mx, 1));
            mx = fmaxf(mx, __shfl_xor_sync(0xffffffffu, mx, 2));
            float mn = fmaxf(mrow[h2], mx);
            float alpha = __expf(mrow[h2] - mn);
            mrow[h2] = mn;
            float rs = 0.f;
#pragma unroll
            for (int nb = 0; nb < 16; nb++) {
                float p0 = __expf(s[nb][h2 * 2]     - mn);
                float p1 = __expf(s[nb][h2 * 2 + 1] - mn);
                s[nb][h2 * 2] = p0; s[nb][h2 * 2 + 1] = p1;
                rs += p0 + p1;
            }
            rs += __shfl_xor_sync(0xffffffffu, rs, 1);
            rs += __shfl_xor_sync(0xffffffffu, rs, 2);
            lrow[h2] = lrow[h2] * alpha + rs;
#pragma unroll
            for (int nbo = 0; nbo < 8; nbo++) {
                o[nbo][h2 * 2]     *= alpha;
                o[nbo][h2 * 2 + 1] *= alpha;
            }
        }

        // ---- O += P V (3 split passes; P from registers, V via ldmatrix.trans) ----
#pragma unroll
        for (int kk = 0; kk < 8; kk++) {
            uint32_t ah[4], al[4];
            split2(s[2 * kk][0],     s[2 * kk][1],     ah[0], al[0]);
            split2(s[2 * kk][2],     s[2 * kk][3],     ah[1], al[1]);
            split2(s[2 * kk + 1][0], s[2 * kk + 1][1], ah[2], al[2]);
            split2(s[2 * kk + 1][2], s[2 * kk + 1][3], ah[3], al[3]);
            const uint32_t laneV = sb + (uint32_t)(
                (kk * 16 + (lane & 15)) * FSTR + (lane >> 4) * 16);
#pragma unroll
            for (int ng = 0; ng < 4; ng++) {
                uint32_t bh4[4], bl4[4];
                LDSM_T4(bh4, laneV + SVH + ng * 32);
                LDSM_T4(bl4, laneV + SVL + ng * 32);
                MMA16816(o[2 * ng],     ah, bh4[0], bh4[1]);
                MMA16816(o[2 * ng + 1], ah, bh4[2], bh4[3]);
                MMA16816(o[2 * ng],     ah, bl4[0], bl4[1]);
                MMA16816(o[2 * ng + 1], ah, bl4[2], bl4[3]);
                MMA16816(o[2 * ng],     al, bh4[0], bh4[1]);
                MMA16816(o[2 * ng + 1], al, bh4[2], bh4[3]);
            }
        }
    }

    // ---- epilogue: normalize, write bf16 hi/lo context [B,S,D] ----
#pragma unroll
    for (int h2 = 0; h2 < 2; h2++) {
        float inv = 1.0f / lrow[h2];
        int srow = q0 + w * 16 + (lane >> 2) + h2 * 8;
        size_t base = (size_t)(b * SEQ + srow) * D_MODEL + h * D_HEAD;
#pragma unroll
        for (int nbo = 0; nbo < 8; nbo++) {
            int dcol = nbo * 8 + (lane & 3) * 2;
            uint32_t hi, lo;
            split2(o[nbo][h2 * 2] * inv, o[nbo][h2 * 2 + 1] * inv, hi, lo);
            *(uint32_t*)&g_chi[base + dcol] = hi;
            *(uint32_t*)&g_clo[base + dcol] = lo;
        }
    }
}

// =====================================================================
extern "C" void kernel_launch(void* const* d_in, const int* in_sizes, int n_in,
                              void* d_out, int out_size)
{
    const float* x  = (const float*)d_in[0];
    const unsigned char* mask = (const unsigned char*)d_in[1];
    const float* wq = (const float*)d_in[2];
    const float* bq = (const float*)d_in[3];
    const float* wk = (const float*)d_in[4];
    const float* bk = (const float*)d_in[5];
    const float* wv = (const float*)d_in[6];
    const float* bv = (const float*)d_in[7];
    const float* wo = (const float*)d_in[8];
    const float* bo = (const float*)d_in[9];
    float* out = (float*)d_out;

    split_all_kernel<<<SPLIT_TOT / 256, 256>>>(x, wq, wk, wv, wo);

    cudaFuncSetAttribute(qkv_mma_kernel, cudaFuncAttributeMaxDynamicSharedMemorySize, GEMM_SMEM);
    qkv_mma_kernel<<<dim3(M_TOT / 128, 24), 256, GEMM_SMEM>>>(bq, bk, bv);

    cudaFuncSetAttribute(flash_mma_kernel, cudaFuncAttributeMaxDynamicSharedMemorySize, FLASH_SMEM);
    flash_mma_kernel<<<dim3(SEQ / 64, BATCH * N_HEADS), 128, FLASH_SMEM>>>(mask);

    cudaFuncSetAttribute(out_mma_kernel, cudaFuncAttributeMaxDynamicSharedMemorySize, GEMM_SMEM);
    out_mma_kernel<<<dim3(M_TOT / 128, 8), 256, GEMM_SMEM>>>(bo, out);
}